// round 1
// baseline (speedup 1.0000x reference)
#include <cuda_runtime.h>
#include <cstdint>

// Problem constants
#define BB 8
#define CC 8
#define HH 512
#define WW 512
#define PLANE (HH*WW)                 // 262144
#define PIX   (BB*HH*WW)              // 2097152 pixels
#define NEL   (BB*CC*HH*WW)           // 16777216 elements (8-channel arrays)

__device__ double g_acc;

__device__ __forceinline__ float sigf(float x) {
    // fast sigmoid: EX2 + fast RCP (2 MUFU)
    return __fdividef(1.0f, 1.0f + __expf(-x));
}

__device__ __forceinline__ float clog(float x) {
    // clamped log, matches jnp.clip(log(x), -100): log(0) = -inf -> -100,
    // NaN (shouldn't happen) -> -100 via fmaxf semantics
    return fmaxf(__logf(x), -100.0f);
}

// sigmoid of neighbor element, 0 if out of bounds (zero-padded shift of the
// PROBABILITY map, per reference)
__device__ __forceinline__ float nsig(const float* __restrict__ xb, int c,
                                      int h, int w, int dh, int dw) {
    int hh = h + dh, ww = w + dw;
    if ((unsigned)hh >= (unsigned)HH || (unsigned)ww >= (unsigned)WW) return 0.0f;
    return sigf(__ldg(xb + c * PLANE + hh * WW + ww));
}

struct BranchRes { float bicon, conn, glo, vmin; };

// Process one branch (atts or dets) for one pixel.
// xb: batch-base pointer [8, H, W]; t: con_target channels (binary).
__device__ __forceinline__ BranchRes branch_eval(const float* __restrict__ xb,
                                                 const float t[8], int h, int w) {
    const float* px = xb + h * WW + w;
    float s[8];
#pragma unroll
    for (int c = 0; c < 8; c++) s[c] = sigf(__ldg(px + c * PLANE));

    // shifted neighbor probabilities
    float n1 = nsig(xb, 4, h, w,  0, -1);   // right        = c4[h, w-1]
    float n2 = nsig(xb, 3, h, w,  0, +1);   // left         = c3[h, w+1]
    float n3 = nsig(xb, 6, h, w, -1,  0);   // bottom       = c6[h-1, w]
    float n4 = nsig(xb, 1, h, w, +1,  0);   // up           = c1[h+1, w]
    float n5 = nsig(xb, 5, h, w, -1, +1);   // left_bottom  = c5[h-1, w+1]
    float n6 = nsig(xb, 2, h, w, +1, -1);   // right_above  = c2[h+1, w-1]
    float n7 = nsig(xb, 7, h, w, -1, -1);   // right_bottom = c7[h-1, w-1]
    float n8 = nsig(xb, 0, h, w, +1, +1);   // left_above   = c0[h+1, w+1]

    float a1 = s[3] * n1;
    float a2 = s[4] * n2;
    float a3 = s[1] * n3;
    float a4 = s[6] * n4;
    float a5 = s[2] * n5;
    float a6 = s[5] * n6;
    float a7 = s[0] * n7;
    float a8 = s[7] * n8;

    // vote_out channel order: [a7, a3, a5, a1, a2, a6, a4, a8]
    float v[8] = {a7, a3, a5, a1, a2, a6, a4, a8};

    float bic = 0.0f, con = 0.0f, glo = 0.0f, mn = v[0];
#pragma unroll
    for (int k = 0; k < 8; k++) {
        glo += v[k];
        mn = fminf(mn, v[k]);
        // t[k] is exactly 0.0f or 1.0f: select the single needed log
        bic += clog(t[k] > 0.5f ? v[k] : 1.0f - v[k]);
        con += clog(t[k] > 0.5f ? s[k] : 1.0f - s[k]);
    }
    BranchRes r;
    r.bicon = bic;
    r.conn  = con;
    r.glo   = glo * 0.125f;
    r.vmin  = mn;
    return r;
}

__global__ void init_acc_kernel() { g_acc = 0.0; }

__global__ void __launch_bounds__(256)
bicon_loss_kernel(const float* __restrict__ atts,
                  const float* __restrict__ dets,
                  const float* __restrict__ target,
                  const float* __restrict__ con) {
    int idx = blockIdx.x * blockDim.x + threadIdx.x;   // pixel id, exactly PIX threads
    int w = idx & (WW - 1);
    int h = (idx >> 9) & (HH - 1);
    int b = idx >> 18;

    const size_t bstride = (size_t)CC * PLANE;
    const float* ab = atts + (size_t)b * bstride;
    const float* db = dets + (size_t)b * bstride;
    const float* cb = con  + (size_t)b * bstride;

    // con_target channels (binary)
    float t[8];
    float sum8 = 0.0f;
    const float* ct = cb + h * WW + w;
#pragma unroll
    for (int c = 0; c < 8; c++) {
        t[c] = __ldg(ct + c * PLANE);
        sum8 += t[c];
    }

    BranchRes r1 = branch_eval(ab, t, h, w);   // atts branch
    BranchRes r2 = branch_eval(db, t, h, w);   // dets branch

    float tg = __ldg(target + (size_t)b * PLANE + h * WW + w);
    bool edge = (sum8 > 0.0f) && (sum8 < 8.0f);

    // decouple map: edge ? (1 - min(vote_out2)) : glo_map2
    float de_p = edge ? (1.0f - r2.vmin) : r2.glo;

    float b1_term = clog(tg > 0.5f ? r1.glo : 1.0f - r1.glo);
    float de_term = clog(tg > 0.5f ? de_p  : 1.0f - de_p);

    const float inv16m = 1.0f / (float)NEL;
    const float inv2m  = 1.0f / (float)PIX;

    float contrib = (0.2f * (r1.bicon + r2.bicon) + 0.8f * (r1.conn + r2.conn)) * inv16m
                  + (b1_term + de_term) * inv2m;

    // block reduction: warp shfl -> smem -> one double atomic per block
    __shared__ float wsum[8];
#pragma unroll
    for (int o = 16; o > 0; o >>= 1)
        contrib += __shfl_down_sync(0xFFFFFFFFu, contrib, o);
    int lane = threadIdx.x & 31;
    int wid  = threadIdx.x >> 5;
    if (lane == 0) wsum[wid] = contrib;
    __syncthreads();
    if (threadIdx.x == 0) {
        float s = 0.0f;
#pragma unroll
        for (int i = 0; i < 8; i++) s += wsum[i];
        atomicAdd(&g_acc, (double)s);
    }
}

__global__ void finalize_kernel(float* out) {
    out[0] = (float)(-g_acc);
}

extern "C" void kernel_launch(void* const* d_in, const int* in_sizes, int n_in,
                              void* d_out, int out_size) {
    const float* atts   = (const float*)d_in[0];
    const float* dets   = (const float*)d_in[1];
    const float* target = (const float*)d_in[2];
    const float* con    = (const float*)d_in[3];
    float* out = (float*)d_out;

    init_acc_kernel<<<1, 1>>>();
    bicon_loss_kernel<<<PIX / 256, 256>>>(atts, dets, target, con);
    finalize_kernel<<<1, 1>>>(out);
}